// round 1
// baseline (speedup 1.0000x reference)
#include <cuda_runtime.h>
#include <cstdint>

#define D_DIM 1024
#define BM 128
#define BN 128
#define BK 16
#define NTHREADS 256

// ---------------- device scratch (no allocations allowed) ----------------
__device__ unsigned long long g_keys[8192];   // (sim_bits << 32) | (~col)
__device__ float g_einv[8192];
__device__ float g_cinv[4096];

// ---------------- kernel: reset per-row argmax keys ----------------
__global__ void init_keys_kernel(int B_) {
    int i = blockIdx.x * blockDim.x + threadIdx.x;
    if (i < B_) g_keys[i] = 0ULL;
}

// ---------------- kernel: inverse L2 norms for rows of emb and cen ----------------
__global__ void norms_kernel(const float* __restrict__ emb,
                             const float* __restrict__ cen,
                             int B_, int C_) {
    int row = blockIdx.x;
    const float* p = (row < B_) ? (emb + (size_t)row * D_DIM)
                                : (cen + (size_t)(row - B_) * D_DIM);
    // 256 threads * float4 = 1024 elements
    float4 v = reinterpret_cast<const float4*>(p)[threadIdx.x];
    float s = v.x * v.x + v.y * v.y + v.z * v.z + v.w * v.w;
#pragma unroll
    for (int m = 16; m >= 1; m >>= 1) s += __shfl_xor_sync(0xffffffffu, s, m);
    __shared__ float ws[8];
    int wid = threadIdx.x >> 5;
    if ((threadIdx.x & 31) == 0) ws[wid] = s;
    __syncthreads();
    if (threadIdx.x == 0) {
        float t = 0.f;
#pragma unroll
        for (int w = 0; w < 8; ++w) t += ws[w];
        float inv = 1.0f / fmaxf(sqrtf(t), 1e-12f);
        if (row < B_) g_einv[row] = inv;
        else          g_cinv[row - B_] = inv;
    }
}

// ---------------- packed fp32x2 helpers ----------------
__device__ __forceinline__ unsigned long long dupf(float x) {
    unsigned long long r;
    asm("mov.b64 %0, {%1, %1};" : "=l"(r) : "f"(x));
    return r;
}
__device__ __forceinline__ void ffma2(unsigned long long& d,
                                      unsigned long long a,
                                      unsigned long long b) {
    asm("fma.rn.f32x2 %0, %1, %2, %0;" : "+l"(d) : "l"(a), "l"(b));
}

// ---------------- fused GEMM + scale + clip + row max/argmax ----------------
__global__ __launch_bounds__(NTHREADS, 2)
void gemm_argmax_kernel(const float* __restrict__ A,
                        const float* __restrict__ Bc,
                        int B_, int C_) {
    __shared__ __align__(16) float As[2][BK][BM + 4];
    __shared__ __align__(16) float Bs[2][BK][BN + 4];

    const int tid = threadIdx.x;
    const int tx  = tid & 15;
    const int ty  = tid >> 4;
    const int tx4 = tx * 4;
    const int ty4 = ty * 4;

    const int rb = blockIdx.y * BM;
    const int cb = blockIdx.x * BN;

    // global-load mapping: each thread loads 2 float4 per matrix per k-tile
    const int lr = tid >> 2;          // 0..63
    const int lk = (tid & 3) * 4;     // 0,4,8,12

    const float* Ap0 = A  + (size_t)(rb + lr)      * D_DIM + lk;
    const float* Ap1 = A  + (size_t)(rb + lr + 64) * D_DIM + lk;
    const float* Bp0 = Bc + (size_t)(cb + lr)      * D_DIM + lk;
    const float* Bp1 = Bc + (size_t)(cb + lr + 64) * D_DIM + lk;

    unsigned long long acc[8][4];
#pragma unroll
    for (int i = 0; i < 8; ++i)
#pragma unroll
        for (int q = 0; q < 4; ++q) acc[i][q] = 0ULL;

    float4 a0 = *(const float4*)(Ap0);
    float4 a1 = *(const float4*)(Ap1);
    float4 b0 = *(const float4*)(Bp0);
    float4 b1 = *(const float4*)(Bp1);

    // stage tile 0
    As[0][lk + 0][lr] = a0.x; As[0][lk + 1][lr] = a0.y;
    As[0][lk + 2][lr] = a0.z; As[0][lk + 3][lr] = a0.w;
    As[0][lk + 0][lr + 64] = a1.x; As[0][lk + 1][lr + 64] = a1.y;
    As[0][lk + 2][lr + 64] = a1.z; As[0][lk + 3][lr + 64] = a1.w;
    Bs[0][lk + 0][lr] = b0.x; Bs[0][lk + 1][lr] = b0.y;
    Bs[0][lk + 2][lr] = b0.z; Bs[0][lk + 3][lr] = b0.w;
    Bs[0][lk + 0][lr + 64] = b1.x; Bs[0][lk + 1][lr + 64] = b1.y;
    Bs[0][lk + 2][lr + 64] = b1.z; Bs[0][lk + 3][lr + 64] = b1.w;
    __syncthreads();

    const int NK = D_DIM / BK;  // 64
    int buf = 0;
    for (int kt = 0; kt < NK; ++kt) {
        if (kt + 1 < NK) {
            const int k0 = (kt + 1) * BK;
            a0 = *(const float4*)(Ap0 + k0);
            a1 = *(const float4*)(Ap1 + k0);
            b0 = *(const float4*)(Bp0 + k0);
            b1 = *(const float4*)(Bp1 + k0);
        }
#pragma unroll
        for (int k = 0; k < BK; ++k) {
            float4 af0 = *(const float4*)&As[buf][k][ty4];
            float4 af1 = *(const float4*)&As[buf][k][64 + ty4];
            ulonglong2 bl0 = *(const ulonglong2*)&Bs[buf][k][tx4];
            ulonglong2 bl1 = *(const ulonglong2*)&Bs[buf][k][64 + tx4];
            unsigned long long ad[8];
            ad[0] = dupf(af0.x); ad[1] = dupf(af0.y);
            ad[2] = dupf(af0.z); ad[3] = dupf(af0.w);
            ad[4] = dupf(af1.x); ad[5] = dupf(af1.y);
            ad[6] = dupf(af1.z); ad[7] = dupf(af1.w);
            unsigned long long bb[4] = {bl0.x, bl0.y, bl1.x, bl1.y};
#pragma unroll
            for (int i = 0; i < 8; ++i)
#pragma unroll
                for (int q = 0; q < 4; ++q) ffma2(acc[i][q], ad[i], bb[q]);
        }
        if (kt + 1 < NK) {
            buf ^= 1;
            As[buf][lk + 0][lr] = a0.x; As[buf][lk + 1][lr] = a0.y;
            As[buf][lk + 2][lr] = a0.z; As[buf][lk + 3][lr] = a0.w;
            As[buf][lk + 0][lr + 64] = a1.x; As[buf][lk + 1][lr + 64] = a1.y;
            As[buf][lk + 2][lr + 64] = a1.z; As[buf][lk + 3][lr + 64] = a1.w;
            Bs[buf][lk + 0][lr] = b0.x; Bs[buf][lk + 1][lr] = b0.y;
            Bs[buf][lk + 2][lr] = b0.z; Bs[buf][lk + 3][lr] = b0.w;
            Bs[buf][lk + 0][lr + 64] = b1.x; Bs[buf][lk + 1][lr + 64] = b1.y;
            Bs[buf][lk + 2][lr + 64] = b1.z; Bs[buf][lk + 3][lr + 64] = b1.w;
        }
        __syncthreads();
    }

    // epilogue: scale by inverse norms, clip to [0,1], per-row max/argmax
#pragma unroll
    for (int i = 0; i < 8; ++i) {
        const int r = rb + ((i < 4) ? (ty4 + i) : (64 + ty4 + i - 4));
        const float einv = g_einv[r];
        float best = -1.0f;
        int bc = 0;
#pragma unroll
        for (int q = 0; q < 4; ++q) {
            const int cbase = cb + ((q < 2) ? (tx4 + q * 2) : (64 + tx4 + (q - 2) * 2));
            union { unsigned long long u; float2 f; } cv;
            cv.u = acc[i][q];
            const float s0 = fminf(fmaxf(cv.f.x * einv * g_cinv[cbase],     0.f), 1.f);
            const float s1 = fminf(fmaxf(cv.f.y * einv * g_cinv[cbase + 1], 0.f), 1.f);
            if (s0 > best) { best = s0; bc = cbase; }
            if (s1 > best) { best = s1; bc = cbase + 1; }
        }
        unsigned long long key =
            ((unsigned long long)__float_as_uint(best) << 32) |
            (unsigned long long)(0xFFFFFFFFu - (unsigned)bc);
#pragma unroll
        for (int m = 8; m >= 1; m >>= 1) {
            unsigned long long o = __shfl_xor_sync(0xffffffffu, key, m);
            if (o > key) key = o;
        }
        if (tx == 0) atomicMax(&g_keys[r], key);
    }
}

// ---------------- kernel: novelty + closest from merged keys ----------------
__global__ void finalize_kernel(float* __restrict__ out, int B_, int twoout) {
    int i = blockIdx.x * blockDim.x + threadIdx.x;
    if (i >= B_) return;
    const unsigned long long key = g_keys[i];
    const float sim = __uint_as_float((unsigned)(key >> 32));  // already clipped [0,1]
    float nov = sqrtf(fmaxf(1.0f - sim, 0.0f));
    nov = fminf(fmaxf(nov, 0.0f), 1.0f);
    const unsigned closest = 0xFFFFFFFFu - (unsigned)(key & 0xFFFFFFFFu);
    out[i] = nov;
    if (twoout) out[B_ + i] = (float)closest;
}

// ---------------- launch ----------------
extern "C" void kernel_launch(void* const* d_in, const int* in_sizes, int n_in,
                              void* d_out, int out_size) {
    const float* emb = (const float*)d_in[0];
    const float* cen = (const float*)d_in[1];
    const int B_ = in_sizes[0] / D_DIM;   // 8192
    const int C_ = in_sizes[1] / D_DIM;   // 4096

    init_keys_kernel<<<(B_ + 255) / 256, 256>>>(B_);
    norms_kernel<<<B_ + C_, 256>>>(emb, cen, B_, C_);

    dim3 grid(C_ / BN, B_ / BM);   // 32 x 64 = 2048 CTAs
    gemm_argmax_kernel<<<grid, NTHREADS>>>(emb, cen, B_, C_);

    const int twoout = (out_size >= 2 * B_) ? 1 : 0;
    finalize_kernel<<<(B_ + 255) / 256, 256>>>((float*)d_out, B_, twoout);
}

// round 3
// speedup vs baseline: 3.0309x; 3.0309x over previous
#include <cuda_runtime.h>
#include <cuda_fp16.h>
#include <cstdint>

#define D_DIM   1024
#define KTOT    3072          // 3 segments x 1024
#define NKB     192           // KTOT / 16 k-blocks
#define NITER   96            // KTOT / 32
#define STAGES  4
#define BM      128
#define BN      128
#define NPA     64            // 8192/128 row panels
#define NPB     32            // 4096/128 col panels

// A panel layout: [pnl][kb(192)][mblk(8)][512B]  -> 4KB per (pnl,kb)
// B panel layout: [pnl][kb(192)][nblk(16)][256B] -> 4KB per (pnl,kb)
#define A_KB_BYTES 4096
#define B_KB_BYTES 4096
#define STAGE_BYTES 16384                 // 2 kb of A + 2 kb of B
#define SMEM_DYN (1024 + STAGES * STAGE_BYTES)

__device__ __align__(128) unsigned char g_A[(size_t)NPA * NKB * A_KB_BYTES]; // 50.3 MB
__device__ __align__(128) unsigned char g_B[(size_t)NPB * NKB * B_KB_BYTES]; // 25.2 MB
__device__ unsigned long long g_keys[8192];

// ---------------- PTX helpers ----------------
__device__ __forceinline__ uint32_t smem_u32(const void* p) {
    uint32_t a;
    asm("{ .reg .u64 t; cvta.to.shared.u64 t, %1; cvt.u32.u64 %0, t; }" : "=r"(a) : "l"(p));
    return a;
}
#define MBAR_INIT(a, n) \
    asm volatile("mbarrier.init.shared.b64 [%0], %1;" :: "r"(a), "r"((uint32_t)(n)) : "memory")
#define MBAR_ARRIVE(a) \
    asm volatile("mbarrier.arrive.shared.b64 _, [%0];" :: "r"(a) : "memory")
#define MBAR_EXPECT_TX(a, b) \
    asm volatile("mbarrier.arrive.expect_tx.shared.b64 _, [%0], %1;" :: "r"(a), "r"((uint32_t)(b)) : "memory")
#define MBAR_WAIT(a, ph) do {                                                      \
    uint32_t _m = (a), _p = (ph), _d;                                              \
    asm volatile("{ .reg .pred p; mbarrier.try_wait.parity.acquire.cta.shared::cta.b64 p, [%1], %2; selp.b32 %0,1,0,p; }" \
        : "=r"(_d) : "r"(_m), "r"(_p) : "memory");                                 \
    if (!_d) {                                                                     \
        asm volatile("{ .reg .pred P; L1_%=: mbarrier.try_wait.parity.acquire.cta.shared::cta.b64 P, [%0], %1, 0x989680; @P bra.uni L2_%=; bra.uni L1_%=; L2_%=: }" \
            :: "r"(_m), "r"(_p) : "memory");                                       \
    }                                                                              \
} while (0)

__device__ __forceinline__ void bulk_g2s(uint32_t dst, const void* src,
                                         uint32_t bytes, uint32_t mbar) {
    asm volatile("cp.async.bulk.shared::cluster.global.mbarrier::complete_tx::bytes [%0], [%1], %2, [%3];"
        :: "r"(dst), "l"(src), "r"(bytes), "r"(mbar) : "memory");
}
__device__ __forceinline__ void hmma(float* d, const uint32_t* a, const uint32_t* b) {
    asm volatile(
        "mma.sync.aligned.m16n8k16.row.col.f32.f16.f16.f32 "
        "{%0,%1,%2,%3}, {%4,%5,%6,%7}, {%8,%9}, {%0,%1,%2,%3};"
        : "+f"(d[0]), "+f"(d[1]), "+f"(d[2]), "+f"(d[3])
        : "r"(a[0]), "r"(a[1]), "r"(a[2]), "r"(a[3]), "r"(b[0]), "r"(b[1]));
}

// ---------------- reset keys ----------------
__global__ void init_keys_kernel(int B_) {
    int i = blockIdx.x * blockDim.x + threadIdx.x;
    if (i < B_) g_keys[i] = 0ULL;
}

// ---------------- normalize + split + fragment-pack ----------------
// A segments along K: [hi | hi | lo]; B segments: [hi | lo | hi]
__global__ void split_kernel(const float* __restrict__ emb,
                             const float* __restrict__ cen, int B_, int C_) {
    const int row = blockIdx.x;
    const bool isA = row < B_;
    const float* p = isA ? emb + (size_t)row * D_DIM
                         : cen + (size_t)(row - B_) * D_DIM;
    float4 v = reinterpret_cast<const float4*>(p)[threadIdx.x];
    float s = v.x * v.x + v.y * v.y + v.z * v.z + v.w * v.w;
#pragma unroll
    for (int m = 16; m >= 1; m >>= 1) s += __shfl_xor_sync(0xffffffffu, s, m);
    __shared__ float ws[8];
    __shared__ float s_inv;
    if ((threadIdx.x & 31) == 0) ws[threadIdx.x >> 5] = s;
    __syncthreads();
    if (threadIdx.x == 0) {
        float t = 0.f;
#pragma unroll
        for (int w = 0; w < 8; ++w) t += ws[w];
        s_inv = 1.0f / fmaxf(sqrtf(t), 1e-12f);
    }
    __syncthreads();
    const float inv = s_inv;

    const float u[4] = {v.x * inv, v.y * inv, v.z * inv, v.w * inv};
    __half h[4], l[4];
#pragma unroll
    for (int j = 0; j < 4; ++j) {
        h[j] = __float2half_rn(u[j]);
        l[j] = __float2half_rn(u[j] - __half2float(h[j]));
    }

    const int k0 = threadIdx.x * 4;
#pragma unroll
    for (int pr = 0; pr < 2; ++pr) {           // two half2 pairs
        const int kk = k0 + 2 * pr;
        const int ks = kk >> 4;                // source k-block (0..63)
        const __half2 hi2 = __halves2half2(h[2 * pr], h[2 * pr + 1]);
        const __half2 lo2 = __halves2half2(l[2 * pr], l[2 * pr + 1]);
        if (isA) {
            const int pnl = row >> 7;
            const int mblk = (row & 127) >> 4;
            const int i = row & 15;
            const int lane = (i & 7) * 4 + ((kk & 7) >> 1);
            const int slot = (i >> 3) + 2 * ((kk & 15) >> 3);
            const uint32_t inoff = (uint32_t)mblk * 512 + lane * 16 + slot * 4;
#define A_ADDR(kb) (g_A + ((size_t)((pnl) * NKB + (kb)) * A_KB_BYTES) + inoff)
            *(__half2*)A_ADDR(ks)        = hi2;
            *(__half2*)A_ADDR(ks + 64)   = hi2;
            *(__half2*)A_ADDR(ks + 128)  = lo2;
#undef A_ADDR
        } else {
            const int c = row - B_;
            const int pnl = c >> 7;
            const int nblk = (c & 127) >> 3;
            const int n = c & 7;
            const int lane = n * 4 + ((kk & 7) >> 1);
            const int slot = (kk & 15) >> 3;
            const uint32_t inoff = (uint32_t)nblk * 256 + lane * 8 + slot * 4;
#define B_ADDR(kb) (g_B + ((size_t)((pnl) * NKB + (kb)) * B_KB_BYTES) + inoff)
            *(__half2*)B_ADDR(ks)        = hi2;
            *(__half2*)B_ADDR(ks + 64)   = lo2;
            *(__half2*)B_ADDR(ks + 128)  = hi2;
#undef B_ADDR
        }
    }
}

// ---------------- HMMA GEMM + fused clip/max/argmax ----------------
__global__ void __launch_bounds__(288, 2) gemm_kernel() {
    extern __shared__ __align__(16) unsigned char smem[];
    const uint32_t sbase = smem_u32(smem);
    const int tid = threadIdx.x;
    const int wid = tid >> 5;
    const int lane = tid & 31;

    const uint32_t mb_full  = sbase;            // 4 x 8B
    const uint32_t mb_empty = sbase + 64;       // 4 x 8B
    const uint32_t tiles    = sbase + 1024;

    if (tid == 0) {
#pragma unroll
        for (int s = 0; s < STAGES; ++s) {
            MBAR_INIT(mb_full + s * 8, 1);
            MBAR_INIT(mb_empty + s * 8, 8);     // 8 consumer warps
        }
    }
    __syncthreads();

    if (wid == 8) {
        // ---- producer ----
        if (lane == 0) {
            const unsigned char* aP = g_A + (size_t)blockIdx.y * NKB * A_KB_BYTES;
            const unsigned char* bP = g_B + (size_t)blockIdx.x * NKB * B_KB_BYTES;
            for (int kt = 0; kt < NITER; ++kt) {
                const int s = kt & (STAGES - 1);
                MBAR_WAIT(mb_empty + s * 8, 1u ^ ((kt >> 2) & 1));
                MBAR_EXPECT_TX(mb_full + s * 8, STAGE_BYTES);
                const uint32_t st = tiles + s * STAGE_BYTES;
                bulk_g2s(st,        aP + (size_t)(2 * kt) * A_KB_BYTES, 2 * A_KB_BYTES,
                         mb_full + s * 8);
                bulk_g2s(st + 8192, bP + (size_t)(2 * kt) * B_KB_BYTES, 2 * B_KB_BYTES,
                         mb_full + s * 8);
            }
        }
        return;
    }

    // ---- consumers: 8 warps, warp tile 64x32 ----
    const int wm = wid & 1;      // M half
    const int wn = wid >> 1;     // N quarter

    float acc[4][4][4];
#pragma unroll
    for (int mi = 0; mi < 4; ++mi)
#pragma unroll
        for (int ni = 0; ni < 4; ++ni)
#pragma unroll
            for (int q = 0; q < 4; ++q) acc[mi][ni][q] = 0.0f;

    const uint32_t aoff = lane * 16;
    const uint32_t boff = lane * 8;

    for (int kt = 0; kt < NITER; ++kt) {
        const int s = kt & (STAGES - 1);
        MBAR_WAIT(mb_full + s * 8, (kt >> 2) & 1);
        const uint32_t stA = tiles + s * STAGE_BYTES;
        const uint32_t stB = stA + 8192;
#pragma unroll
        for (int s16 = 0; s16 < 2; ++s16) {
            uint32_t a[4][4], b[4][2];
#pragma unroll
            for (int mi = 0; mi < 4; ++mi) {
                const uint32_t ad = stA + (uint32_t)(s16 * 8 + wm * 4 + mi) * 512 + aoff;
                asm volatile("ld.shared.v4.b32 {%0,%1,%2,%3}, [%4];"
                    : "=r"(a[mi][0]), "=r"(a[mi][1]), "=r"(a[mi][2]), "=r"(a[mi][3])
                    : "r"(ad));
            }
#pragma unroll
            for (int ni = 0; ni < 4; ++ni) {
                const uint32_t bd = stB + (uint32_t)(s16 * 16 + wn * 4 + ni) * 256 + boff;
                asm volatile("ld.shared.v2.b32 {%0,%1}, [%2];"
                    : "=r"(b[ni][0]), "=r"(b[ni][1]) : "r"(bd));
            }
#pragma unroll
            for (int mi = 0; mi < 4; ++mi)
#pragma unroll
                for (int ni = 0; ni < 4; ++ni)
                    hmma(acc[mi][ni], a[mi], b[ni]);
        }
        if (lane == 0) MBAR_ARRIVE(mb_empty + s * 8);
    }

    // ---- epilogue: clip, row max/argmax, merge ----
    const int rowbase = blockIdx.y * BM + wm * 64;
    const int colbase = blockIdx.x * BN + wn * 32 + (lane & 3) * 2;
#pragma unroll
    for (int mi = 0; mi < 4; ++mi) {
#pragma unroll
        for (int ih = 0; ih < 2; ++ih) {
            float best = -1.0f;
            int bc = 0;
#pragma unroll
            for (int ni = 0; ni < 4; ++ni) {
                const int c = colbase + ni * 8;
                const float s0 = fminf(fmaxf(acc[mi][ni][ih * 2 + 0], 0.f), 1.f);
                const float s1 = fminf(fmaxf(acc[mi][ni][ih * 2 + 1], 0.f), 1.f);
                if (s0 > best) { best = s0; bc = c; }
                if (s1 > best) { best = s1; bc = c + 1; }
            }
            unsigned long long key =
                ((unsigned long long)__float_as_uint(best) << 32) |
                (unsigned long long)(0xFFFFFFFFu - (unsigned)bc);
#pragma unroll
            for (int m = 2; m >= 1; m >>= 1) {
                unsigned long long o = __shfl_xor_sync(0xffffffffu, key, m);
                if (o > key) key = o;
            }
            if ((lane & 3) == 0) {
                const int r = rowbase + mi * 16 + ih * 8 + (lane >> 2);
                atomicMax(&g_keys[r], key);
            }
        }
    }
}

// ---------------- finalize ----------------
__global__ void finalize_kernel(float* __restrict__ out, int B_, int twoout) {
    int i = blockIdx.x * blockDim.x + threadIdx.x;
    if (i >= B_) return;
    const unsigned long long key = g_keys[i];
    const float sim = __uint_as_float((unsigned)(key >> 32));
    float nov = sqrtf(fmaxf(1.0f - sim, 0.0f));
    nov = fminf(fmaxf(nov, 0.0f), 1.0f);
    const unsigned closest = 0xFFFFFFFFu - (unsigned)(key & 0xFFFFFFFFu);
    out[i] = nov;
    if (twoout) out[B_ + i] = (float)closest;
}

// ---------------- launch ----------------
extern "C" void kernel_launch(void* const* d_in, const int* in_sizes, int n_in,
                              void* d_out, int out_size) {
    const float* emb = (const float*)d_in[0];
    const float* cen = (const float*)d_in[1];
    const int B_ = in_sizes[0] / D_DIM;   // 8192
    const int C_ = in_sizes[1] / D_DIM;   // 4096

    init_keys_kernel<<<(B_ + 255) / 256, 256>>>(B_);
    split_kernel<<<B_ + C_, 256>>>(emb, cen, B_, C_);

    cudaFuncSetAttribute(gemm_kernel,
                         cudaFuncAttributeMaxDynamicSharedMemorySize, SMEM_DYN);
    dim3 grid(C_ / BN, B_ / BM);          // 32 x 64 = 2048 CTAs
    gemm_kernel<<<grid, 288, SMEM_DYN>>>();

    const int twoout = (out_size >= 2 * B_) ? 1 : 0;
    finalize_kernel<<<(B_ + 255) / 256, 256>>>((float*)d_out, B_, twoout);
}

// round 4
// speedup vs baseline: 7.4195x; 2.4479x over previous
#include <cuda_runtime.h>
#include <cuda_fp16.h>
#include <cstdint>

#define D_DIM   1024
#define NKB     64            // 1024/16 k-blocks
#define NITER   32            // 1024/32
#define STAGES  4
#define BM      128
#define BN      128
#define NPA     64            // 8192/128 row panels
#define NPB     32            // 4096/128 col panels

#define A_KB_BYTES 4096
#define B_KB_BYTES 4096
#define STAGE_BYTES 16384
#define SMEM_DYN (1024 + STAGES * STAGE_BYTES)
#define DELTA 1e-4f

__device__ __align__(128) unsigned char g_A[(size_t)NPA * NKB * A_KB_BYTES]; // 16.8 MB
__device__ __align__(128) unsigned char g_B[(size_t)NPB * NKB * B_KB_BYTES]; // 8.4 MB
__device__ unsigned long long g_cands[(size_t)8192 * 256];                    // 16 MB
__device__ float g_einv[8192];
__device__ float g_cinv[4096];

// ---------------- PTX helpers ----------------
__device__ __forceinline__ uint32_t smem_u32(const void* p) {
    uint32_t a;
    asm("{ .reg .u64 t; cvta.to.shared.u64 t, %1; cvt.u32.u64 %0, t; }" : "=r"(a) : "l"(p));
    return a;
}
#define MBAR_INIT(a, n) \
    asm volatile("mbarrier.init.shared.b64 [%0], %1;" :: "r"(a), "r"((uint32_t)(n)) : "memory")
#define MBAR_ARRIVE(a) \
    asm volatile("mbarrier.arrive.shared.b64 _, [%0];" :: "r"(a) : "memory")
#define MBAR_EXPECT_TX(a, b) \
    asm volatile("mbarrier.arrive.expect_tx.shared.b64 _, [%0], %1;" :: "r"(a), "r"((uint32_t)(b)) : "memory")
#define MBAR_WAIT(a, ph) do {                                                      \
    uint32_t _m = (a), _p = (ph), _d;                                              \
    asm volatile("{ .reg .pred p; mbarrier.try_wait.parity.acquire.cta.shared::cta.b64 p, [%1], %2; selp.b32 %0,1,0,p; }" \
        : "=r"(_d) : "r"(_m), "r"(_p) : "memory");                                 \
    if (!_d) {                                                                     \
        asm volatile("{ .reg .pred P; L1_%=: mbarrier.try_wait.parity.acquire.cta.shared::cta.b64 P, [%0], %1, 0x989680; @P bra.uni L2_%=; bra.uni L1_%=; L2_%=: }" \
            :: "r"(_m), "r"(_p) : "memory");                                       \
    }                                                                              \
} while (0)

__device__ __forceinline__ void bulk_g2s(uint32_t dst, const void* src,
                                         uint32_t bytes, uint32_t mbar) {
    asm volatile("cp.async.bulk.shared::cluster.global.mbarrier::complete_tx::bytes [%0], [%1], %2, [%3];"
        :: "r"(dst), "l"(src), "r"(bytes), "r"(mbar) : "memory");
}
__device__ __forceinline__ void hmma(float* d, const uint32_t* a, const uint32_t* b) {
    asm volatile(
        "mma.sync.aligned.m16n8k16.row.col.f32.f16.f16.f32 "
        "{%0,%1,%2,%3}, {%4,%5,%6,%7}, {%8,%9}, {%0,%1,%2,%3};"
        : "+f"(d[0]), "+f"(d[1]), "+f"(d[2]), "+f"(d[3])
        : "r"(a[0]), "r"(a[1]), "r"(a[2]), "r"(a[3]), "r"(b[0]), "r"(b[1]));
}
__device__ __forceinline__ unsigned long long enc_key(float sim, int col) {
    return ((unsigned long long)__float_as_uint(sim) << 32) |
           (unsigned long long)(0xFFFFFFFFu - (unsigned)col);
}

// ---------------- normalize + fp16 fragment-pack (hi only) ----------------
__global__ void split_kernel(const float* __restrict__ emb,
                             const float* __restrict__ cen, int B_, int C_) {
    const int row = blockIdx.x;
    const bool isA = row < B_;
    const float* p = isA ? emb + (size_t)row * D_DIM
                         : cen + (size_t)(row - B_) * D_DIM;
    float4 v = reinterpret_cast<const float4*>(p)[threadIdx.x];
    float s = v.x * v.x + v.y * v.y + v.z * v.z + v.w * v.w;
#pragma unroll
    for (int m = 16; m >= 1; m >>= 1) s += __shfl_xor_sync(0xffffffffu, s, m);
    __shared__ float ws[8];
    __shared__ float s_inv;
    if ((threadIdx.x & 31) == 0) ws[threadIdx.x >> 5] = s;
    __syncthreads();
    if (threadIdx.x == 0) {
        float t = 0.f;
#pragma unroll
        for (int w = 0; w < 8; ++w) t += ws[w];
        s_inv = 1.0f / fmaxf(sqrtf(t), 1e-12f);
        if (isA) g_einv[row] = s_inv;
        else     g_cinv[row - B_] = s_inv;
    }
    __syncthreads();
    const float inv = s_inv;

    const float u[4] = {v.x * inv, v.y * inv, v.z * inv, v.w * inv};
    __half h[4];
#pragma unroll
    for (int j = 0; j < 4; ++j) h[j] = __float2half_rn(u[j]);

    const int k0 = threadIdx.x * 4;
#pragma unroll
    for (int pr = 0; pr < 2; ++pr) {
        const int kk = k0 + 2 * pr;
        const int ks = kk >> 4;
        const __half2 hi2 = __halves2half2(h[2 * pr], h[2 * pr + 1]);
        if (isA) {
            const int pnl = row >> 7;
            const int mblk = (row & 127) >> 4;
            const int i = row & 15;
            const int lane = (i & 7) * 4 + ((kk & 7) >> 1);
            const int slot = (i >> 3) + 2 * ((kk & 15) >> 3);
            *(__half2*)(g_A + ((size_t)(pnl * NKB + ks) * A_KB_BYTES) +
                        (uint32_t)mblk * 512 + lane * 16 + slot * 4) = hi2;
        } else {
            const int c = row - B_;
            const int pnl = c >> 7;
            const int nblk = (c & 127) >> 3;
            const int n = c & 7;
            const int lane = n * 4 + ((kk & 7) >> 1);
            const int slot = (kk & 15) >> 3;
            *(__half2*)(g_B + ((size_t)(pnl * NKB + ks) * B_KB_BYTES) +
                        (uint32_t)nblk * 256 + lane * 8 + slot * 4) = hi2;
        }
    }
}

// ---------------- HMMA GEMM + per-(row, warp-quarter) top-2 candidates ----------------
__global__ void __launch_bounds__(288, 2) gemm_kernel() {
    extern __shared__ __align__(16) unsigned char smem[];
    const uint32_t sbase = smem_u32(smem);
    const int tid = threadIdx.x;
    const int wid = tid >> 5;
    const int lane = tid & 31;

    const uint32_t mb_full  = sbase;
    const uint32_t mb_empty = sbase + 64;
    const uint32_t tiles    = sbase + 1024;

    if (tid == 0) {
#pragma unroll
        for (int s = 0; s < STAGES; ++s) {
            MBAR_INIT(mb_full + s * 8, 1);
            MBAR_INIT(mb_empty + s * 8, 8);
        }
    }
    __syncthreads();

    if (wid == 8) {
        if (lane == 0) {
            const unsigned char* aP = g_A + (size_t)blockIdx.y * NKB * A_KB_BYTES;
            const unsigned char* bP = g_B + (size_t)blockIdx.x * NKB * B_KB_BYTES;
            for (int kt = 0; kt < NITER; ++kt) {
                const int s = kt & (STAGES - 1);
                MBAR_WAIT(mb_empty + s * 8, 1u ^ ((kt >> 2) & 1));
                MBAR_EXPECT_TX(mb_full + s * 8, STAGE_BYTES);
                const uint32_t st = tiles + s * STAGE_BYTES;
                bulk_g2s(st,        aP + (size_t)(2 * kt) * A_KB_BYTES, 2 * A_KB_BYTES,
                         mb_full + s * 8);
                bulk_g2s(st + 8192, bP + (size_t)(2 * kt) * B_KB_BYTES, 2 * B_KB_BYTES,
                         mb_full + s * 8);
            }
        }
        return;
    }

    const int wm = wid & 1;
    const int wn = wid >> 1;

    float acc[4][4][4];
#pragma unroll
    for (int mi = 0; mi < 4; ++mi)
#pragma unroll
        for (int ni = 0; ni < 4; ++ni)
#pragma unroll
            for (int q = 0; q < 4; ++q) acc[mi][ni][q] = 0.0f;

    const uint32_t aoff = lane * 16;
    const uint32_t boff = lane * 8;

    for (int kt = 0; kt < NITER; ++kt) {
        const int s = kt & (STAGES - 1);
        MBAR_WAIT(mb_full + s * 8, (kt >> 2) & 1);
        const uint32_t stA = tiles + s * STAGE_BYTES;
        const uint32_t stB = stA + 8192;
#pragma unroll
        for (int s16 = 0; s16 < 2; ++s16) {
            uint32_t a[4][4], b[4][2];
#pragma unroll
            for (int mi = 0; mi < 4; ++mi) {
                const uint32_t ad = stA + (uint32_t)(s16 * 8 + wm * 4 + mi) * 512 + aoff;
                asm volatile("ld.shared.v4.b32 {%0,%1,%2,%3}, [%4];"
                    : "=r"(a[mi][0]), "=r"(a[mi][1]), "=r"(a[mi][2]), "=r"(a[mi][3])
                    : "r"(ad));
            }
#pragma unroll
            for (int ni = 0; ni < 4; ++ni) {
                const uint32_t bd = stB + (uint32_t)(s16 * 16 + wn * 4 + ni) * 256 + boff;
                asm volatile("ld.shared.v2.b32 {%0,%1}, [%2];"
                    : "=r"(b[ni][0]), "=r"(b[ni][1]) : "r"(bd));
            }
#pragma unroll
            for (int mi = 0; mi < 4; ++mi)
#pragma unroll
                for (int ni = 0; ni < 4; ++ni)
                    hmma(acc[mi][ni], a[mi], b[ni]);
        }
        if (lane == 0) MBAR_ARRIVE(mb_empty + s * 8);
    }

    // ---- epilogue: top-2 per (row, 32-col quarter), no atomics ----
    const int rowbase = blockIdx.y * BM + wm * 64;
    const int colbase = blockIdx.x * BN + wn * 32 + (lane & 3) * 2;
#pragma unroll
    for (int mi = 0; mi < 4; ++mi) {
#pragma unroll
        for (int ih = 0; ih < 2; ++ih) {
            unsigned long long k1 = 0ULL, k2 = 0ULL;
#pragma unroll
            for (int ni = 0; ni < 4; ++ni) {
#pragma unroll
                for (int j = 0; j < 2; ++j) {
                    const float sim =
                        fminf(fmaxf(acc[mi][ni][ih * 2 + j], 0.f), 1.f);
                    const unsigned long long key = enc_key(sim, colbase + ni * 8 + j);
                    if (key > k1) { k2 = k1; k1 = key; }
                    else if (key > k2) { k2 = key; }
                }
            }
#pragma unroll
            for (int m = 1; m <= 2; m <<= 1) {
                const unsigned long long o1 = __shfl_xor_sync(0xffffffffu, k1, m);
                const unsigned long long o2 = __shfl_xor_sync(0xffffffffu, k2, m);
                if (o1 > k1) { k2 = (k1 > o2) ? k1 : o2; k1 = o1; }
                else         { k2 = (k2 > o1) ? k2 : o1; }
            }
            if ((lane & 3) == 0) {
                const int r = rowbase + mi * 16 + ih * 8 + (lane >> 2);
                ulonglong2 kk; kk.x = k1; kk.y = k2;
                *(ulonglong2*)&g_cands[(size_t)r * 256 + blockIdx.x * 8 + wn * 2] = kk;
            }
        }
    }
}

// ---------------- rescore: pick argmax, exact fp32 for near-ties ----------------
__global__ void __launch_bounds__(256) rescore_kernel(
    const float* __restrict__ emb, const float* __restrict__ cen,
    float* __restrict__ out, int B_, int twoout) {
    __shared__ unsigned long long list[8][16];
    __shared__ int lcnt[8];

    const int w = threadIdx.x >> 5;
    const int lane = threadIdx.x & 31;
    const int row = blockIdx.x * 8 + w;
    if (row >= B_) return;

    unsigned long long k[8];
#pragma unroll
    for (int j = 0; j < 8; ++j)
        k[j] = g_cands[(size_t)row * 256 + j * 32 + lane];

    unsigned long long kmax = 0ULL;
#pragma unroll
    for (int j = 0; j < 8; ++j) if (k[j] > kmax) kmax = k[j];
#pragma unroll
    for (int m = 16; m >= 1; m >>= 1) {
        const unsigned long long o = __shfl_xor_sync(0xffffffffu, kmax, m);
        if (o > kmax) kmax = o;
    }
    const float smax = __uint_as_float((unsigned)(kmax >> 32));
    const float th = smax - DELTA;

    int cnt = 0;
#pragma unroll
    for (int j = 0; j < 8; ++j)
        cnt += (__uint_as_float((unsigned)(k[j] >> 32)) >= th) ? 1 : 0;
#pragma unroll
    for (int m = 16; m >= 1; m >>= 1) cnt += __shfl_xor_sync(0xffffffffu, cnt, m);

    float bsim;
    unsigned bcol;
    if (cnt <= 1) {
        bsim = smax;
        bcol = 0xFFFFFFFFu - (unsigned)(kmax & 0xFFFFFFFFu);
    } else {
        if (lane == 0) lcnt[w] = 0;
        __syncwarp();
#pragma unroll
        for (int j = 0; j < 8; ++j) {
            if (__uint_as_float((unsigned)(k[j] >> 32)) >= th) {
                const int pos = atomicAdd(&lcnt[w], 1);
                if (pos < 16) list[w][pos] = k[j];
            }
        }
        __syncwarp();
        const int n = min(lcnt[w], 16);

        float4 e[8];
        const float4* e4 = (const float4*)(emb + (size_t)row * D_DIM);
#pragma unroll
        for (int t = 0; t < 8; ++t) e[t] = e4[t * 32 + lane];
        const float einv = g_einv[row];

        unsigned long long bestk = 0ULL;
        for (int i = 0; i < n; ++i) {
            const unsigned col = 0xFFFFFFFFu - (unsigned)(list[w][i] & 0xFFFFFFFFu);
            const float4* c4 = (const float4*)(cen + (size_t)col * D_DIM);
            float d = 0.f;
#pragma unroll
            for (int t = 0; t < 8; ++t) {
                const float4 cv = c4[t * 32 + lane];
                d += e[t].x * cv.x + e[t].y * cv.y + e[t].z * cv.z + e[t].w * cv.w;
            }
#pragma unroll
            for (int m = 16; m >= 1; m >>= 1) d += __shfl_xor_sync(0xffffffffu, d, m);
            const float sim = fminf(fmaxf(d * einv * g_cinv[col], 0.f), 1.f);
            const unsigned long long key = enc_key(sim, (int)col);
            if (key > bestk) bestk = key;
        }
        bsim = __uint_as_float((unsigned)(bestk >> 32));
        bcol = 0xFFFFFFFFu - (unsigned)(bestk & 0xFFFFFFFFu);
    }

    if (lane == 0) {
        float nov = sqrtf(fmaxf(1.0f - bsim, 0.0f));
        out[row] = fminf(fmaxf(nov, 0.0f), 1.0f);
        if (twoout) out[B_ + row] = (float)bcol;
    }
}

// ---------------- launch ----------------
extern "C" void kernel_launch(void* const* d_in, const int* in_sizes, int n_in,
                              void* d_out, int out_size) {
    const float* emb = (const float*)d_in[0];
    const float* cen = (const float*)d_in[1];
    const int B_ = in_sizes[0] / D_DIM;   // 8192
    const int C_ = in_sizes[1] / D_DIM;   // 4096

    split_kernel<<<B_ + C_, 256>>>(emb, cen, B_, C_);

    cudaFuncSetAttribute(gemm_kernel,
                         cudaFuncAttributeMaxDynamicSharedMemorySize, SMEM_DYN);
    dim3 grid(C_ / BN, B_ / BM);          // 32 x 64 = 2048 CTAs
    gemm_kernel<<<grid, 288, SMEM_DYN>>>();

    const int twoout = (out_size >= 2 * B_) ? 1 : 0;
    rescore_kernel<<<(B_ + 7) / 8, 256>>>(emb, cen, (float*)d_out, B_, twoout);
}